// round 11
// baseline (speedup 1.0000x reference)
#include <cuda_runtime.h>
#include <cuda_fp16.h>
#include <cstdint>

// Problem constants
#define Bn 8
#define Hn 224
#define Wn 224
#define Cn 64
#define IN_DIM 576
#define RANKn 100
#define FILTERS 256
#define HW 50176            // 224*224
#define XTOT (Bn * Hn * Wn * Cn)
#define NCONVBLK (XTOT / 8 / 256)     // 3136 convert blocks

// GEMM tiling: CTA 128x128, 4 warps (2M x 2N), warp tile 64x64
#define CTA_M 128
#define CTA_N 128
#define BK 64                         // one full 3x3 tap (64 ch)
#define NT 128
#define KITERS (IN_DIM / BK)          // 9
#define STAGE_BYTES 32768             // A 16KB + B 16KB (fp16)
#define NSTAGE 3
#define SM_TOTAL (NSTAGE * STAGE_BYTES)  // 96KB -> 2 CTAs/SM

// Scratch (device globals; no allocation allowed)
__device__ __half g_Wh[FILTERS * IN_DIM];   // [n][k] fp16
__device__ __half g_xh[XTOT];               // x in fp16, same layout

// ---------------------------------------------------------------------------
__device__ __forceinline__ uint32_t smem_u32(const void* p) {
    uint32_t a;
    asm("{ .reg .u64 t; cvta.to.shared.u64 t, %1; cvt.u32.u64 %0, t; }"
        : "=r"(a) : "l"(p));
    return a;
}
#define CP_ASYNC_Z(d, s, sz) \
    asm volatile("cp.async.cg.shared.global [%0], [%1], 16, %2;" \
                 :: "r"(d), "l"(s), "r"(sz))
#define CP_ASYNC16(d, s) \
    asm volatile("cp.async.cg.shared.global [%0], [%1], 16;" :: "r"(d), "l"(s))
#define CP_COMMIT() asm volatile("cp.async.commit_group;" ::: "memory")
#define CP_WAIT(n)  asm volatile("cp.async.wait_group %0;" :: "n"(n) : "memory")

#define LDSM_X4(r0, r1, r2, r3, a) \
    asm volatile("ldmatrix.sync.aligned.m8n8.x4.shared.b16 {%0,%1,%2,%3}, [%4];" \
                 : "=r"(r0), "=r"(r1), "=r"(r2), "=r"(r3) : "r"(a))

#define MMA_F16(c, a, b0, b1)                                               \
    asm volatile("mma.sync.aligned.m16n8k16.row.col.f32.f16.f16.f32 "       \
                 "{%0,%1,%2,%3}, {%4,%5,%6,%7}, {%8,%9}, {%0,%1,%2,%3};"    \
                 : "+f"((c)[0]), "+f"((c)[1]), "+f"((c)[2]), "+f"((c)[3])   \
                 : "r"((a)[0]), "r"((a)[1]), "r"((a)[2]), "r"((a)[3]),      \
                   "r"(b0), "r"(b1))

// ---------------------------------------------------------------------------
// Fused prep (one launch):
//   blocks [0, NCONVBLK)          : convert x -> fp16 (g_xh)
//   blocks [NCONVBLK, +FILTERS)   : build g_Wh row n = fp16( U @ (fold) col n )
//     step 0: W[:,n] = k     @ aux_Vt[:,n]
//     step 1: W[:,n] = aux_U @ l_t[:,n]
//     step 2: W[:,n] = aux_Unp1 @ (s @ aux_Vtnp1)[:,n]
// ---------------------------------------------------------------------------
__global__ void prep_all(const float* __restrict__ x,
                         const float* __restrict__ k_,
                         const float* __restrict__ l_t,
                         const float* __restrict__ s,
                         const float* __restrict__ aux_U,
                         const float* __restrict__ aux_Unp1,
                         const float* __restrict__ aux_Vt,
                         const float* __restrict__ aux_Vtnp1,
                         const int* __restrict__ step_p) {
    if (blockIdx.x < NCONVBLK) {
        int idx = blockIdx.x * 256 + threadIdx.x;   // one per 8 floats
        const float4* xp = reinterpret_cast<const float4*>(x) + idx * 2;
        float4 v0 = xp[0], v1 = xp[1];
        __half2 h[4];
        h[0] = __float22half2_rn(make_float2(v0.x, v0.y));
        h[1] = __float22half2_rn(make_float2(v0.z, v0.w));
        h[2] = __float22half2_rn(make_float2(v1.x, v1.y));
        h[3] = __float22half2_rn(make_float2(v1.z, v1.w));
        *reinterpret_cast<uint4*>(g_xh + (size_t)idx * 8) =
            *reinterpret_cast<uint4*>(h);
        return;
    }
    // ---- weight-fold branch: one block per output filter n ----
    __shared__ float VtCol[RANKn];
    __shared__ float Ms[RANKn];
    const int n   = blockIdx.x - NCONVBLK;
    const int tid = threadIdx.x;
    const int st  = *step_p;

    if (st == 2) {
        if (tid < RANKn) VtCol[tid] = aux_Vtnp1[(size_t)tid * FILTERS + n];
        __syncthreads();
        if (tid < RANKn) {
            const float* sr = s + (size_t)tid * RANKn;
            float acc = 0.f;
            #pragma unroll 4
            for (int q = 0; q < RANKn; ++q) acc += sr[q] * VtCol[q];
            Ms[tid] = acc;
        }
    } else {
        const float* V = (st == 0) ? aux_Vt : l_t;
        if (tid < RANKn) Ms[tid] = V[(size_t)tid * FILTERS + n];
    }
    __syncthreads();

    const float* U = (st == 0) ? k_ : (st == 1) ? aux_U : aux_Unp1;
    for (int k = tid; k < IN_DIM; k += 256) {
        const float* ur = U + (size_t)k * RANKn;
        float acc = 0.f;
        #pragma unroll 4
        for (int r = 0; r < RANKn; ++r) acc += ur[r] * Ms[r];
        g_Wh[(size_t)n * IN_DIM + k] = __float2half_rn(acc);
    }
}

// ---------------------------------------------------------------------------
// Main: fp16 mma.sync implicit-GEMM conv  (R7 body — measured optimum)
// CTA: 128 pixels x 128 filters; 4 warps (2M x 2N), warp tile 64x64.
// 3-stage cp.async ring, one barrier per K-iter, 2 CTAs/SM.
// ---------------------------------------------------------------------------
__global__ void __launch_bounds__(NT, 2)
conv_main(const float* __restrict__ bias_b,
          const float* __restrict__ bias_aux,
          const int* __restrict__ step_p,
          float* __restrict__ out) {
    extern __shared__ __align__(128) char smem[];
    const int tid  = threadIdx.x;
    const int lane = tid & 31;
    const int wid  = tid >> 5;
    const int mwarp = wid >> 1;       // 0..1
    const int nwarp = wid & 1;        // 0..1
    const int Mbase = blockIdx.x * CTA_M;
    const int Nbase = blockIdx.y * CTA_N;
    const uint32_t sb = smem_u32(smem);

    // Loader geometry: chunk j = tid&7, row group rA = tid>>3 (0..15)
    const int jA  = tid & 7;
    const int rA  = tid >> 3;
    int hL[8], wL[8], bL[8];
    #pragma unroll
    for (int l = 0; l < 8; ++l) {
        int p = Mbase + l * 16 + rA;
        int bi = p / HW;
        int rem = p - bi * HW;
        hL[l] = rem / Wn;
        wL[l] = rem - hL[l] * Wn;
        bL[l] = bi;
    }

    float acc[4][8][4];
    #pragma unroll
    for (int mt = 0; mt < 4; ++mt)
        #pragma unroll
        for (int nt = 0; nt < 8; ++nt)
            #pragma unroll
            for (int q = 0; q < 4; ++q) acc[mt][nt][q] = 0.f;

    auto load_stage = [&](int ko) {
        const int stage = ko % NSTAGE;
        const int dh = ko / 3 - 1;
        const int dw = ko % 3 - 1;
        const uint32_t dA = sb + stage * STAGE_BYTES;
        #pragma unroll
        for (int l = 0; l < 8; ++l) {
            const int row = l * 16 + rA;
            const int hh = hL[l] + dh;
            const int ww = wL[l] + dw;
            const bool ok = ((unsigned)hh < (unsigned)Hn) &&
                            ((unsigned)ww < (unsigned)Wn);
            const __half* sp = ok
                ? g_xh + (((size_t)bL[l] * Hn + hh) * Wn + ww) * Cn + jA * 8
                : g_xh;
            CP_ASYNC_Z(dA + row * 128 + ((jA ^ (row & 7)) << 4), sp, ok ? 16u : 0u);
        }
        const int k0 = ko * BK;
        const uint32_t dB = dA + 16384;
        #pragma unroll
        for (int l = 0; l < 8; ++l) {
            const int n = l * 16 + rA;
            const __half* bs = g_Wh + (size_t)(Nbase + n) * IN_DIM + k0 + jA * 8;
            CP_ASYNC16(dB + n * 128 + ((jA ^ (n & 7)) << 4), bs);
        }
    };

    // Fragment addressing
    const int m7  = lane & 7;
    const int khA = lane >> 4;               // A chunk parity
    const int khB = (lane >> 3) & 1;         // B chunk parity
    const uint32_t arow = (uint32_t)(mwarp * 64 + (lane & 15)) * 128;
    const uint32_t brow = (uint32_t)(nwarp * 64 + ((lane >> 4) << 3) + m7) * 128;
    uint32_t coffA[4], coffB[4];
    #pragma unroll
    for (int ks = 0; ks < 4; ++ks) {
        coffA[ks] = (uint32_t)(((ks * 2 + khA) ^ m7) << 4);
        coffB[ks] = (uint32_t)(((ks * 2 + khB) ^ m7) << 4);
    }

    load_stage(0); CP_COMMIT();
    load_stage(1); CP_COMMIT();

    for (int ko = 0; ko < KITERS; ++ko) {
        if (ko < KITERS - 1) CP_WAIT(1);
        else                 CP_WAIT(0);
        __syncthreads();
        if (ko + 2 < KITERS) { load_stage(ko + 2); CP_COMMIT(); }

        const uint32_t As = sb + (ko % NSTAGE) * STAGE_BYTES;
        const uint32_t Bs = As + 16384;

        #pragma unroll
        for (int ks = 0; ks < 4; ++ks) {
            uint32_t bf[4][4];
            #pragma unroll
            for (int np = 0; np < 4; ++np)
                LDSM_X4(bf[np][0], bf[np][1], bf[np][2], bf[np][3],
                        Bs + brow + np * (16 * 128) + coffB[ks]);
            uint32_t a[4][4];
            #pragma unroll
            for (int mt = 0; mt < 4; ++mt)
                LDSM_X4(a[mt][0], a[mt][1], a[mt][2], a[mt][3],
                        As + arow + mt * (16 * 128) + coffA[ks]);
            #pragma unroll
            for (int mt = 0; mt < 4; ++mt)
                #pragma unroll
                for (int nt = 0; nt < 8; ++nt)
                    MMA_F16(acc[mt][nt], a[mt],
                            bf[nt >> 1][(nt & 1) * 2],
                            bf[nt >> 1][(nt & 1) * 2 + 1]);
        }
    }

    // Epilogue: bias + relu + store
    const float* bias = (*step_p == 2) ? bias_b : bias_aux;
    const int g  = lane >> 2;
    const int tq = lane & 3;
    #pragma unroll
    for (int mt = 0; mt < 4; ++mt) {
        const int r0 = Mbase + mwarp * 64 + mt * 16 + g;
        #pragma unroll
        for (int half = 0; half < 2; ++half) {
            const int r = r0 + half * 8;
            const int bi = r / HW;
            const int rr = r - bi * HW;
            const float* bp = bias + (size_t)rr * FILTERS;
            float* op = out + (size_t)r * FILTERS;
            #pragma unroll
            for (int nt = 0; nt < 8; ++nt) {
                const int col = Nbase + nwarp * 64 + nt * 8 + tq * 2;
                const float2 bv = *reinterpret_cast<const float2*>(bp + col);
                float2 o;
                o.x = fmaxf(acc[mt][nt][half * 2 + 0] + bv.x, 0.f);
                o.y = fmaxf(acc[mt][nt][half * 2 + 1] + bv.y, 0.f);
                *reinterpret_cast<float2*>(op + col) = o;
            }
        }
    }
}

// ---------------------------------------------------------------------------
// Inputs: 0:x 1:k 2:l_t 3:s 4:aux_U 5:aux_Unp1 6:aux_Vt 7:aux_Vtnp1
//         8:b 9:aux_b 10:step
// ---------------------------------------------------------------------------
extern "C" void kernel_launch(void* const* d_in, const int* in_sizes, int n_in,
                              void* d_out, int out_size) {
    const float* x         = (const float*)d_in[0];
    const float* k_        = (const float*)d_in[1];
    const float* l_t       = (const float*)d_in[2];
    const float* s         = (const float*)d_in[3];
    const float* aux_U     = (const float*)d_in[4];
    const float* aux_Unp1  = (const float*)d_in[5];
    const float* aux_Vt    = (const float*)d_in[6];
    const float* aux_Vtnp1 = (const float*)d_in[7];
    const float* bias_b    = (const float*)d_in[8];
    const float* bias_aux  = (const float*)d_in[9];
    const int*   step_p    = (const int*)d_in[10];
    float* out = (float*)d_out;

    prep_all<<<NCONVBLK + FILTERS, 256>>>(x, k_, l_t, s, aux_U, aux_Unp1,
                                          aux_Vt, aux_Vtnp1, step_p);

    static bool cfg_done = false;
    if (!cfg_done) {
        cudaFuncSetAttribute(conv_main,
                             cudaFuncAttributeMaxDynamicSharedMemorySize, SM_TOTAL);
        cfg_done = true;
    }
    dim3 grid((Bn * Hn * Wn) / CTA_M, FILTERS / CTA_N);   // (3136, 2)
    conv_main<<<grid, NT, SM_TOTAL>>>(bias_b, bias_aux, step_p, out);
}

// round 12
// speedup vs baseline: 1.0773x; 1.0773x over previous
#include <cuda_runtime.h>
#include <cuda_fp16.h>
#include <cstdint>

// Problem constants
#define Bn 8
#define Hn 224
#define Wn 224
#define Cn 64
#define IN_DIM 576
#define RANKn 100
#define FILTERS 256
#define HW 50176            // 224*224
#define XTOT (Bn * Hn * Wn * Cn)          // 25690112
#define NCONVBLK (XTOT / 16 / 256)        // 6272 conversion blocks (16 floats/thr)

// GEMM tiling: CTA 128x128, 4 warps (2M x 2N), warp tile 64x64
#define CTA_M 128
#define CTA_N 128
#define BK 64                         // one full 3x3 tap (64 ch)
#define NT 128
#define KITERS (IN_DIM / BK)          // 9
#define STAGE_BYTES 32768             // A 16KB + B 16KB (fp16)
#define NSTAGE 3
#define SM_TOTAL (NSTAGE * STAGE_BYTES)  // 96KB -> 2 CTAs/SM

// Scratch (device globals; no allocation allowed)
__device__ __half g_Wh[FILTERS * IN_DIM];   // [n][k] fp16
__device__ __half g_xh[XTOT];               // x in fp16, same layout

// ---------------------------------------------------------------------------
__device__ __forceinline__ uint32_t smem_u32(const void* p) {
    uint32_t a;
    asm("{ .reg .u64 t; cvta.to.shared.u64 t, %1; cvt.u32.u64 %0, t; }"
        : "=r"(a) : "l"(p));
    return a;
}
#define CP_ASYNC_Z(d, s, sz) \
    asm volatile("cp.async.cg.shared.global [%0], [%1], 16, %2;" \
                 :: "r"(d), "l"(s), "r"(sz))
#define CP_ASYNC16(d, s) \
    asm volatile("cp.async.cg.shared.global [%0], [%1], 16;" :: "r"(d), "l"(s))
#define CP_COMMIT() asm volatile("cp.async.commit_group;" ::: "memory")
#define CP_WAIT(n)  asm volatile("cp.async.wait_group %0;" :: "n"(n) : "memory")

#define LDSM_X4(r0, r1, r2, r3, a) \
    asm volatile("ldmatrix.sync.aligned.m8n8.x4.shared.b16 {%0,%1,%2,%3}, [%4];" \
                 : "=r"(r0), "=r"(r1), "=r"(r2), "=r"(r3) : "r"(a))

#define MMA_F16(c, a, b0, b1)                                               \
    asm volatile("mma.sync.aligned.m16n8k16.row.col.f32.f16.f16.f32 "       \
                 "{%0,%1,%2,%3}, {%4,%5,%6,%7}, {%8,%9}, {%0,%1,%2,%3};"    \
                 : "+f"((c)[0]), "+f"((c)[1]), "+f"((c)[2]), "+f"((c)[3])   \
                 : "r"((a)[0]), "r"((a)[1]), "r"((a)[2]), "r"((a)[3]),      \
                   "r"(b0), "r"(b1))

// ---------------------------------------------------------------------------
// Fused prep (one launch, reg-capped so the DRAM-bound branch keeps occupancy):
//   blocks [0, FILTERS)                : build g_Wh row n (fold + project)
//   blocks [FILTERS, FILTERS+NCONVBLK) : convert x -> fp16 (16 floats/thread)
// ---------------------------------------------------------------------------
__global__ void __launch_bounds__(256, 8)
prep_all(const float* __restrict__ x,
         const float* __restrict__ k_,
         const float* __restrict__ l_t,
         const float* __restrict__ s,
         const float* __restrict__ aux_U,
         const float* __restrict__ aux_Unp1,
         const float* __restrict__ aux_Vt,
         const float* __restrict__ aux_Vtnp1,
         const int* __restrict__ step_p) {
    const int tid = threadIdx.x;
    if (blockIdx.x >= FILTERS) {
        // ---- x conversion: 16 consecutive floats per thread ----
        size_t idx = ((size_t)(blockIdx.x - FILTERS) * 256 + tid) * 16;
        const float4* xp = reinterpret_cast<const float4*>(x + idx);
        #pragma unroll
        for (int h = 0; h < 2; ++h) {
            float4 v0 = xp[h * 2 + 0];
            float4 v1 = xp[h * 2 + 1];
            __half2 hh[4];
            hh[0] = __float22half2_rn(make_float2(v0.x, v0.y));
            hh[1] = __float22half2_rn(make_float2(v0.z, v0.w));
            hh[2] = __float22half2_rn(make_float2(v1.x, v1.y));
            hh[3] = __float22half2_rn(make_float2(v1.z, v1.w));
            *reinterpret_cast<uint4*>(g_xh + idx + h * 8) =
                *reinterpret_cast<uint4*>(hh);
        }
        return;
    }
    // ---- weight-fold branch: one block per output filter n ----
    __shared__ float VtCol[RANKn];
    __shared__ float Ms[RANKn];
    const int n  = blockIdx.x;
    const int st = *step_p;

    if (st == 2) {
        if (tid < RANKn) VtCol[tid] = aux_Vtnp1[(size_t)tid * FILTERS + n];
        __syncthreads();
        if (tid < RANKn) {
            const float* sr = s + (size_t)tid * RANKn;
            float acc = 0.f;
            for (int q = 0; q < RANKn; ++q) acc += sr[q] * VtCol[q];
            Ms[tid] = acc;
        }
    } else {
        const float* V = (st == 0) ? aux_Vt : l_t;
        if (tid < RANKn) Ms[tid] = V[(size_t)tid * FILTERS + n];
    }
    __syncthreads();

    const float* U = (st == 0) ? k_ : (st == 1) ? aux_U : aux_Unp1;
    for (int k = tid; k < IN_DIM; k += 256) {
        const float* ur = U + (size_t)k * RANKn;
        float acc = 0.f;
        for (int r = 0; r < RANKn; ++r) acc += ur[r] * Ms[r];
        g_Wh[(size_t)n * IN_DIM + k] = __float2half_rn(acc);
    }
}

// ---------------------------------------------------------------------------
// Main: fp16 mma.sync implicit-GEMM conv  (R7 body — measured optimum, DO NOT EDIT)
// CTA: 128 pixels x 128 filters; 4 warps (2M x 2N), warp tile 64x64.
// 3-stage cp.async ring, one barrier per K-iter, 2 CTAs/SM.
// ---------------------------------------------------------------------------
__global__ void __launch_bounds__(NT, 2)
conv_main(const float* __restrict__ bias_b,
          const float* __restrict__ bias_aux,
          const int* __restrict__ step_p,
          float* __restrict__ out) {
    extern __shared__ __align__(128) char smem[];
    const int tid  = threadIdx.x;
    const int lane = tid & 31;
    const int wid  = tid >> 5;
    const int mwarp = wid >> 1;       // 0..1
    const int nwarp = wid & 1;        // 0..1
    const int Mbase = blockIdx.x * CTA_M;
    const int Nbase = blockIdx.y * CTA_N;
    const uint32_t sb = smem_u32(smem);

    // Loader geometry: chunk j = tid&7, row group rA = tid>>3 (0..15)
    const int jA  = tid & 7;
    const int rA  = tid >> 3;
    int hL[8], wL[8], bL[8];
    #pragma unroll
    for (int l = 0; l < 8; ++l) {
        int p = Mbase + l * 16 + rA;
        int bi = p / HW;
        int rem = p - bi * HW;
        hL[l] = rem / Wn;
        wL[l] = rem - hL[l] * Wn;
        bL[l] = bi;
    }

    float acc[4][8][4];
    #pragma unroll
    for (int mt = 0; mt < 4; ++mt)
        #pragma unroll
        for (int nt = 0; nt < 8; ++nt)
            #pragma unroll
            for (int q = 0; q < 4; ++q) acc[mt][nt][q] = 0.f;

    auto load_stage = [&](int ko) {
        const int stage = ko % NSTAGE;
        const int dh = ko / 3 - 1;
        const int dw = ko % 3 - 1;
        const uint32_t dA = sb + stage * STAGE_BYTES;
        #pragma unroll
        for (int l = 0; l < 8; ++l) {
            const int row = l * 16 + rA;
            const int hh = hL[l] + dh;
            const int ww = wL[l] + dw;
            const bool ok = ((unsigned)hh < (unsigned)Hn) &&
                            ((unsigned)ww < (unsigned)Wn);
            const __half* sp = ok
                ? g_xh + (((size_t)bL[l] * Hn + hh) * Wn + ww) * Cn + jA * 8
                : g_xh;
            CP_ASYNC_Z(dA + row * 128 + ((jA ^ (row & 7)) << 4), sp, ok ? 16u : 0u);
        }
        const int k0 = ko * BK;
        const uint32_t dB = dA + 16384;
        #pragma unroll
        for (int l = 0; l < 8; ++l) {
            const int n = l * 16 + rA;
            const __half* bs = g_Wh + (size_t)(Nbase + n) * IN_DIM + k0 + jA * 8;
            CP_ASYNC16(dB + n * 128 + ((jA ^ (n & 7)) << 4), bs);
        }
    };

    // Fragment addressing
    const int m7  = lane & 7;
    const int khA = lane >> 4;               // A chunk parity
    const int khB = (lane >> 3) & 1;         // B chunk parity
    const uint32_t arow = (uint32_t)(mwarp * 64 + (lane & 15)) * 128;
    const uint32_t brow = (uint32_t)(nwarp * 64 + ((lane >> 4) << 3) + m7) * 128;
    uint32_t coffA[4], coffB[4];
    #pragma unroll
    for (int ks = 0; ks < 4; ++ks) {
        coffA[ks] = (uint32_t)(((ks * 2 + khA) ^ m7) << 4);
        coffB[ks] = (uint32_t)(((ks * 2 + khB) ^ m7) << 4);
    }

    load_stage(0); CP_COMMIT();
    load_stage(1); CP_COMMIT();

    for (int ko = 0; ko < KITERS; ++ko) {
        if (ko < KITERS - 1) CP_WAIT(1);
        else                 CP_WAIT(0);
        __syncthreads();
        if (ko + 2 < KITERS) { load_stage(ko + 2); CP_COMMIT(); }

        const uint32_t As = sb + (ko % NSTAGE) * STAGE_BYTES;
        const uint32_t Bs = As + 16384;

        #pragma unroll
        for (int ks = 0; ks < 4; ++ks) {
            uint32_t bf[4][4];
            #pragma unroll
            for (int np = 0; np < 4; ++np)
                LDSM_X4(bf[np][0], bf[np][1], bf[np][2], bf[np][3],
                        Bs + brow + np * (16 * 128) + coffB[ks]);
            uint32_t a[4][4];
            #pragma unroll
            for (int mt = 0; mt < 4; ++mt)
                LDSM_X4(a[mt][0], a[mt][1], a[mt][2], a[mt][3],
                        As + arow + mt * (16 * 128) + coffA[ks]);
            #pragma unroll
            for (int mt = 0; mt < 4; ++mt)
                #pragma unroll
                for (int nt = 0; nt < 8; ++nt)
                    MMA_F16(acc[mt][nt], a[mt],
                            bf[nt >> 1][(nt & 1) * 2],
                            bf[nt >> 1][(nt & 1) * 2 + 1]);
        }
    }

    // Epilogue: bias + relu + store
    const float* bias = (*step_p == 2) ? bias_b : bias_aux;
    const int g  = lane >> 2;
    const int tq = lane & 3;
    #pragma unroll
    for (int mt = 0; mt < 4; ++mt) {
        const int r0 = Mbase + mwarp * 64 + mt * 16 + g;
        #pragma unroll
        for (int half = 0; half < 2; ++half) {
            const int r = r0 + half * 8;
            const int bi = r / HW;
            const int rr = r - bi * HW;
            const float* bp = bias + (size_t)rr * FILTERS;
            float* op = out + (size_t)r * FILTERS;
            #pragma unroll
            for (int nt = 0; nt < 8; ++nt) {
                const int col = Nbase + nwarp * 64 + nt * 8 + tq * 2;
                const float2 bv = *reinterpret_cast<const float2*>(bp + col);
                float2 o;
                o.x = fmaxf(acc[mt][nt][half * 2 + 0] + bv.x, 0.f);
                o.y = fmaxf(acc[mt][nt][half * 2 + 1] + bv.y, 0.f);
                *reinterpret_cast<float2*>(op + col) = o;
            }
        }
    }
}

// ---------------------------------------------------------------------------
// Inputs: 0:x 1:k 2:l_t 3:s 4:aux_U 5:aux_Unp1 6:aux_Vt 7:aux_Vtnp1
//         8:b 9:aux_b 10:step
// ---------------------------------------------------------------------------
extern "C" void kernel_launch(void* const* d_in, const int* in_sizes, int n_in,
                              void* d_out, int out_size) {
    const float* x         = (const float*)d_in[0];
    const float* k_        = (const float*)d_in[1];
    const float* l_t       = (const float*)d_in[2];
    const float* s         = (const float*)d_in[3];
    const float* aux_U     = (const float*)d_in[4];
    const float* aux_Unp1  = (const float*)d_in[5];
    const float* aux_Vt    = (const float*)d_in[6];
    const float* aux_Vtnp1 = (const float*)d_in[7];
    const float* bias_b    = (const float*)d_in[8];
    const float* bias_aux  = (const float*)d_in[9];
    const int*   step_p    = (const int*)d_in[10];
    float* out = (float*)d_out;

    prep_all<<<FILTERS + NCONVBLK, 256>>>(x, k_, l_t, s, aux_U, aux_Unp1,
                                          aux_Vt, aux_Vtnp1, step_p);

    static bool cfg_done = false;
    if (!cfg_done) {
        cudaFuncSetAttribute(conv_main,
                             cudaFuncAttributeMaxDynamicSharedMemorySize, SM_TOTAL);
        cfg_done = true;
    }
    dim3 grid((Bn * Hn * Wn) / CTA_M, FILTERS / CTA_N);   // (3136, 2)
    conv_main<<<grid, NT, SM_TOTAL>>>(bias_b, bias_aux, step_p, out);
}

// round 13
// speedup vs baseline: 1.2660x; 1.1752x over previous
#include <cuda_runtime.h>
#include <cuda_fp16.h>
#include <cstdint>

// Problem constants
#define Bn 8
#define Hn 224
#define Wn 224
#define Cn 64
#define IN_DIM 576
#define RANKn 100
#define RPAD 128                      // rank padded to 128
#define FILTERS 256
#define HW 50176
#define PIX (Bn * HW)                 // 401408 pixels
#define XTOT (PIX * Cn)
#define NCONVBLK (XTOT / 16 / 256)    // 6272 conversion blocks
#define NFOLD (RPAD + FILTERS)        // 384 fold blocks

// Stage-1 tiling (R7-proven): CTA 128 pixels x 128 rank, 4 warps 2x2, 64x64
#define CTA_M 128
#define BK 64
#define NT 128
#define KITERS (IN_DIM / BK)          // 9
#define STAGE_BYTES 32768
#define NSTAGE 3
#define SM1_TOTAL (NSTAGE * STAGE_BYTES)   // 96KB
// Stage-2: single-shot K=128
#define SM2_TOTAL 65536                    // A 32KB + B 32KB

// Device-global scratch
__device__ __half g_Uh[RPAD * IN_DIM];     // U^T padded  [r][k]
__device__ __half g_M2h[FILTERS * RPAD];   // M^T padded  [n][r]
__device__ __half g_xh[XTOT];              // x fp16
__device__ __half g_z1[(size_t)PIX * RPAD];// intermediate

// ---------------------------------------------------------------------------
__device__ __forceinline__ uint32_t smem_u32(const void* p) {
    uint32_t a;
    asm("{ .reg .u64 t; cvta.to.shared.u64 t, %1; cvt.u32.u64 %0, t; }"
        : "=r"(a) : "l"(p));
    return a;
}
#define CP_ASYNC_Z(d, s, sz) \
    asm volatile("cp.async.cg.shared.global [%0], [%1], 16, %2;" \
                 :: "r"(d), "l"(s), "r"(sz))
#define CP_ASYNC16(d, s) \
    asm volatile("cp.async.cg.shared.global [%0], [%1], 16;" :: "r"(d), "l"(s))
#define CP_COMMIT() asm volatile("cp.async.commit_group;" ::: "memory")
#define CP_WAIT(n)  asm volatile("cp.async.wait_group %0;" :: "n"(n) : "memory")

#define LDSM_X4(r0, r1, r2, r3, a) \
    asm volatile("ldmatrix.sync.aligned.m8n8.x4.shared.b16 {%0,%1,%2,%3}, [%4];" \
                 : "=r"(r0), "=r"(r1), "=r"(r2), "=r"(r3) : "r"(a))

#define MMA_F16(c, a, b0, b1)                                               \
    asm volatile("mma.sync.aligned.m16n8k16.row.col.f32.f16.f16.f32 "       \
                 "{%0,%1,%2,%3}, {%4,%5,%6,%7}, {%8,%9}, {%0,%1,%2,%3};"    \
                 : "+f"((c)[0]), "+f"((c)[1]), "+f"((c)[2]), "+f"((c)[3])   \
                 : "r"((a)[0]), "r"((a)[1]), "r"((a)[2]), "r"((a)[3]),      \
                   "r"(b0), "r"(b1))

// ---------------------------------------------------------------------------
// Fused prep: blocks [0,RPAD) build U^T rows; [RPAD,NFOLD) build M^T rows;
//             [NFOLD, +NCONVBLK) convert x -> fp16 (16 floats/thread).
// ---------------------------------------------------------------------------
__global__ void __launch_bounds__(256, 8)
prep_all(const float* __restrict__ x,
         const float* __restrict__ k_,
         const float* __restrict__ l_t,
         const float* __restrict__ s,
         const float* __restrict__ aux_U,
         const float* __restrict__ aux_Unp1,
         const float* __restrict__ aux_Vt,
         const float* __restrict__ aux_Vtnp1,
         const int* __restrict__ step_p) {
    const int tid = threadIdx.x;
    if (blockIdx.x >= NFOLD) {
        size_t idx = ((size_t)(blockIdx.x - NFOLD) * 256 + tid) * 16;
        const float4* xp = reinterpret_cast<const float4*>(x + idx);
        #pragma unroll
        for (int h = 0; h < 2; ++h) {
            float4 v0 = xp[h * 2 + 0];
            float4 v1 = xp[h * 2 + 1];
            __half2 hh[4];
            hh[0] = __float22half2_rn(make_float2(v0.x, v0.y));
            hh[1] = __float22half2_rn(make_float2(v0.z, v0.w));
            hh[2] = __float22half2_rn(make_float2(v1.x, v1.y));
            hh[3] = __float22half2_rn(make_float2(v1.z, v1.w));
            *reinterpret_cast<uint4*>(g_xh + idx + h * 8) =
                *reinterpret_cast<uint4*>(hh);
        }
        return;
    }
    const int st = *step_p;
    if (blockIdx.x < RPAD) {
        // U^T row r: g_Uh[r][k] = U[k][r]  (zero-pad r >= RANKn)
        const int r = blockIdx.x;
        const float* U = (st == 0) ? k_ : (st == 1) ? aux_U : aux_Unp1;
        for (int k = tid; k < IN_DIM; k += 256) {
            float v = (r < RANKn) ? U[(size_t)k * RANKn + r] : 0.f;
            g_Uh[(size_t)r * IN_DIM + k] = __float2half_rn(v);
        }
        return;
    }
    // M^T row n: g_M2h[n][r] = M[r][n], M = Vt / l_t / s@aux_Vtnp1
    __shared__ float VtCol[RANKn];
    __shared__ float Ms[RANKn];
    const int n = blockIdx.x - RPAD;
    if (st == 2) {
        if (tid < RANKn) VtCol[tid] = aux_Vtnp1[(size_t)tid * FILTERS + n];
        __syncthreads();
        if (tid < RANKn) {
            const float* sr = s + (size_t)tid * RANKn;
            float acc = 0.f;
            for (int q = 0; q < RANKn; ++q) acc += sr[q] * VtCol[q];
            Ms[tid] = acc;
        }
    } else {
        const float* V = (st == 0) ? aux_Vt : l_t;
        if (tid < RANKn) Ms[tid] = V[(size_t)tid * FILTERS + n];
    }
    __syncthreads();
    if (tid < RPAD)
        g_M2h[(size_t)n * RPAD + tid] =
            (tid < RANKn) ? __float2half_rn(Ms[tid]) : __float2half_rn(0.f);
}

// ---------------------------------------------------------------------------
// Stage 1: z1[pix][128] = patches @ U^T   (R7 conv body, N fixed = 128)
// ---------------------------------------------------------------------------
__global__ void __launch_bounds__(NT, 2)
z1k() {
    extern __shared__ __align__(128) char smem[];
    const int tid  = threadIdx.x;
    const int lane = tid & 31;
    const int wid  = tid >> 5;
    const int mwarp = wid >> 1;
    const int nwarp = wid & 1;
    const int Mbase = blockIdx.x * CTA_M;
    const uint32_t sb = smem_u32(smem);

    const int jA  = tid & 7;
    const int rA  = tid >> 3;
    int hL[8], wL[8], bL[8];
    #pragma unroll
    for (int l = 0; l < 8; ++l) {
        int p = Mbase + l * 16 + rA;
        int bi = p / HW;
        int rem = p - bi * HW;
        hL[l] = rem / Wn;
        wL[l] = rem - hL[l] * Wn;
        bL[l] = bi;
    }

    float acc[4][8][4];
    #pragma unroll
    for (int mt = 0; mt < 4; ++mt)
        #pragma unroll
        for (int nt = 0; nt < 8; ++nt)
            #pragma unroll
            for (int q = 0; q < 4; ++q) acc[mt][nt][q] = 0.f;

    auto load_stage = [&](int ko) {
        const int stage = ko % NSTAGE;
        const int dh = ko / 3 - 1;
        const int dw = ko % 3 - 1;
        const uint32_t dA = sb + stage * STAGE_BYTES;
        #pragma unroll
        for (int l = 0; l < 8; ++l) {
            const int row = l * 16 + rA;
            const int hh = hL[l] + dh;
            const int ww = wL[l] + dw;
            const bool ok = ((unsigned)hh < (unsigned)Hn) &&
                            ((unsigned)ww < (unsigned)Wn);
            const __half* sp = ok
                ? g_xh + (((size_t)bL[l] * Hn + hh) * Wn + ww) * Cn + jA * 8
                : g_xh;
            CP_ASYNC_Z(dA + row * 128 + ((jA ^ (row & 7)) << 4), sp, ok ? 16u : 0u);
        }
        const int k0 = ko * BK;
        const uint32_t dB = dA + 16384;
        #pragma unroll
        for (int l = 0; l < 8; ++l) {
            const int n = l * 16 + rA;
            const __half* bs = g_Uh + (size_t)n * IN_DIM + k0 + jA * 8;
            CP_ASYNC16(dB + n * 128 + ((jA ^ (n & 7)) << 4), bs);
        }
    };

    const int m7  = lane & 7;
    const int khA = lane >> 4;
    const int khB = (lane >> 3) & 1;
    const uint32_t arow = (uint32_t)(mwarp * 64 + (lane & 15)) * 128;
    const uint32_t brow = (uint32_t)(nwarp * 64 + ((lane >> 4) << 3) + m7) * 128;
    uint32_t coffA[4], coffB[4];
    #pragma unroll
    for (int ks = 0; ks < 4; ++ks) {
        coffA[ks] = (uint32_t)(((ks * 2 + khA) ^ m7) << 4);
        coffB[ks] = (uint32_t)(((ks * 2 + khB) ^ m7) << 4);
    }

    load_stage(0); CP_COMMIT();
    load_stage(1); CP_COMMIT();

    for (int ko = 0; ko < KITERS; ++ko) {
        if (ko < KITERS - 1) CP_WAIT(1);
        else                 CP_WAIT(0);
        __syncthreads();
        if (ko + 2 < KITERS) { load_stage(ko + 2); CP_COMMIT(); }

        const uint32_t As = sb + (ko % NSTAGE) * STAGE_BYTES;
        const uint32_t Bs = As + 16384;
        #pragma unroll
        for (int ks = 0; ks < 4; ++ks) {
            uint32_t bf[4][4];
            #pragma unroll
            for (int np = 0; np < 4; ++np)
                LDSM_X4(bf[np][0], bf[np][1], bf[np][2], bf[np][3],
                        Bs + brow + np * (16 * 128) + coffB[ks]);
            uint32_t a[4][4];
            #pragma unroll
            for (int mt = 0; mt < 4; ++mt)
                LDSM_X4(a[mt][0], a[mt][1], a[mt][2], a[mt][3],
                        As + arow + mt * (16 * 128) + coffA[ks]);
            #pragma unroll
            for (int mt = 0; mt < 4; ++mt)
                #pragma unroll
                for (int nt = 0; nt < 8; ++nt)
                    MMA_F16(acc[mt][nt], a[mt],
                            bf[nt >> 1][(nt & 1) * 2],
                            bf[nt >> 1][(nt & 1) * 2 + 1]);
        }
    }

    // Epilogue: fp16 z1 store
    const int g  = lane >> 2;
    const int tq = lane & 3;
    #pragma unroll
    for (int mt = 0; mt < 4; ++mt) {
        #pragma unroll
        for (int half = 0; half < 2; ++half) {
            const int r = Mbase + mwarp * 64 + mt * 16 + g + half * 8;
            __half* zp = g_z1 + (size_t)r * RPAD;
            #pragma unroll
            for (int nt = 0; nt < 8; ++nt) {
                const int col = nwarp * 64 + nt * 8 + tq * 2;
                __half2 v = __floats2half2_rn(acc[mt][nt][half * 2 + 0],
                                              acc[mt][nt][half * 2 + 1]);
                *reinterpret_cast<__half2*>(zp + col) = v;
            }
        }
    }
}

// ---------------------------------------------------------------------------
// Stage 2: out = relu(z1 @ M^T + bias). K=128 single-shot, CTA 128x128.
// smem rows are 256B (16 chunks), swizzle chunk^(row&7).
// ---------------------------------------------------------------------------
__global__ void __launch_bounds__(NT, 2)
gemm2(const float* __restrict__ bias_b,
      const float* __restrict__ bias_aux,
      const int* __restrict__ step_p,
      float* __restrict__ out) {
    extern __shared__ __align__(128) char smem[];
    const int tid  = threadIdx.x;
    const int lane = tid & 31;
    const int wid  = tid >> 5;
    const int mwarp = wid >> 1;
    const int nwarp = wid & 1;
    const int Mbase = blockIdx.x * CTA_M;
    const int Nbase = blockIdx.y * 128;
    const uint32_t sb = smem_u32(smem);
    const uint32_t sbB = sb + 32768;

    // Load A (z1 tile) and B (M^T tile): 128 rows x 256B each
    #pragma unroll
    for (int l = 0; l < 16; ++l) {
        int idx = l * NT + tid;
        int row = idx >> 4, j = idx & 15;
        const __half* asrc = g_z1 + (size_t)(Mbase + row) * RPAD + j * 8;
        CP_ASYNC16(sb + row * 256 + ((j ^ (row & 7)) << 4), asrc);
    }
    #pragma unroll
    for (int l = 0; l < 16; ++l) {
        int idx = l * NT + tid;
        int row = idx >> 4, j = idx & 15;
        const __half* bsrc = g_M2h + (size_t)(Nbase + row) * RPAD + j * 8;
        CP_ASYNC16(sbB + row * 256 + ((j ^ (row & 7)) << 4), bsrc);
    }
    CP_COMMIT();

    float acc[4][8][4];
    #pragma unroll
    for (int mt = 0; mt < 4; ++mt)
        #pragma unroll
        for (int nt = 0; nt < 8; ++nt)
            #pragma unroll
            for (int q = 0; q < 4; ++q) acc[mt][nt][q] = 0.f;

    const int m7  = lane & 7;
    const int khA = lane >> 4;
    const int khB = (lane >> 3) & 1;
    const uint32_t arow = (uint32_t)(mwarp * 64 + (lane & 15)) * 256;
    const uint32_t brow = (uint32_t)(nwarp * 64 + ((lane >> 4) << 3) + m7) * 256;

    CP_WAIT(0);
    __syncthreads();

    #pragma unroll
    for (int ks = 0; ks < 8; ++ks) {
        const uint32_t cA = (uint32_t)(((ks * 2 + khA) ^ m7) << 4);
        const uint32_t cB = (uint32_t)(((ks * 2 + khB) ^ m7) << 4);
        uint32_t bf[4][4];
        #pragma unroll
        for (int np = 0; np < 4; ++np)
            LDSM_X4(bf[np][0], bf[np][1], bf[np][2], bf[np][3],
                    sbB + brow + np * (16 * 256) + cB);
        uint32_t a[4][4];
        #pragma unroll
        for (int mt = 0; mt < 4; ++mt)
            LDSM_X4(a[mt][0], a[mt][1], a[mt][2], a[mt][3],
                    sb + arow + mt * (16 * 256) + cA);
        #pragma unroll
        for (int mt = 0; mt < 4; ++mt)
            #pragma unroll
            for (int nt = 0; nt < 8; ++nt)
                MMA_F16(acc[mt][nt], a[mt],
                        bf[nt >> 1][(nt & 1) * 2],
                        bf[nt >> 1][(nt & 1) * 2 + 1]);
    }

    // Epilogue: bias + relu + store
    const float* bias = (*step_p == 2) ? bias_b : bias_aux;
    const int g  = lane >> 2;
    const int tq = lane & 3;
    #pragma unroll
    for (int mt = 0; mt < 4; ++mt) {
        const int r0 = Mbase + mwarp * 64 + mt * 16 + g;
        #pragma unroll
        for (int half = 0; half < 2; ++half) {
            const int r = r0 + half * 8;
            const int bi = r / HW;
            const int rr = r - bi * HW;
            const float* bp = bias + (size_t)rr * FILTERS;
            float* op = out + (size_t)r * FILTERS;
            #pragma unroll
            for (int nt = 0; nt < 8; ++nt) {
                const int col = Nbase + nwarp * 64 + nt * 8 + tq * 2;
                const float2 bv = *reinterpret_cast<const float2*>(bp + col);
                float2 o;
                o.x = fmaxf(acc[mt][nt][half * 2 + 0] + bv.x, 0.f);
                o.y = fmaxf(acc[mt][nt][half * 2 + 1] + bv.y, 0.f);
                *reinterpret_cast<float2*>(op + col) = o;
            }
        }
    }
}

// ---------------------------------------------------------------------------
// Inputs: 0:x 1:k 2:l_t 3:s 4:aux_U 5:aux_Unp1 6:aux_Vt 7:aux_Vtnp1
//         8:b 9:aux_b 10:step
// ---------------------------------------------------------------------------
extern "C" void kernel_launch(void* const* d_in, const int* in_sizes, int n_in,
                              void* d_out, int out_size) {
    const float* x         = (const float*)d_in[0];
    const float* k_        = (const float*)d_in[1];
    const float* l_t       = (const float*)d_in[2];
    const float* s         = (const float*)d_in[3];
    const float* aux_U     = (const float*)d_in[4];
    const float* aux_Unp1  = (const float*)d_in[5];
    const float* aux_Vt    = (const float*)d_in[6];
    const float* aux_Vtnp1 = (const float*)d_in[7];
    const float* bias_b    = (const float*)d_in[8];
    const float* bias_aux  = (const float*)d_in[9];
    const int*   step_p    = (const int*)d_in[10];
    float* out = (float*)d_out;

    static bool cfg_done = false;
    if (!cfg_done) {
        cudaFuncSetAttribute(z1k,
                             cudaFuncAttributeMaxDynamicSharedMemorySize, SM1_TOTAL);
        cudaFuncSetAttribute(gemm2,
                             cudaFuncAttributeMaxDynamicSharedMemorySize, SM2_TOTAL);
        cfg_done = true;
    }

    prep_all<<<NFOLD + NCONVBLK, 256>>>(x, k_, l_t, s, aux_U, aux_Unp1,
                                        aux_Vt, aux_Vtnp1, step_p);
    z1k<<<PIX / CTA_M, NT, SM1_TOTAL>>>();
    dim3 g2(PIX / CTA_M, FILTERS / 128);   // (3136, 2)
    gemm2<<<g2, NT, SM2_TOTAL>>>(bias_b, bias_aux, step_p, out);
}